// round 2
// baseline (speedup 1.0000x reference)
#include <cuda_runtime.h>
#include <cuda_bf16.h>
#include <math.h>

// ----------------------------------------------------------------------------
// FNO-GNO forward, sm_103a. All fp32. Spectral conv implemented as partial
// separable DFT over the 864 used modes (no cuFFT -> no allocations).
// ----------------------------------------------------------------------------

#define S 54
#define S2 2916            // 54*54
#define S3 157464          // 54^3
#define CH 86
#define CS 13541904        // 86 * S3
#define DD 48
#define NOUT 110592        // 48^3
#define NIN 8192
#define KNB 24
#define RTOT 196608        // NIN*KNB
#define MO 6
#define F12 12
#define Q72 72             // 12*6
#define NMODE 864          // 12*12*6
#define WLAYER 6390144     // 4*216*86*86 (float2 per layer)
#define EPSGN 1e-5

// ---------------- device scratch (static globals; allocation-free) ----------
__device__ float  g_h   [CS];
__device__ float  g_skip[CS];
__device__ float  g_hf  [CS];
__device__ float  g_t1  [CS];
__device__ float2 g_A1[CH*S2*MO];      // 1,504,656
__device__ float2 g_A2[CH*S*Q72];      //   334,368
__device__ float2 g_A3[CH*NMODE];      //    74,304
__device__ float2 g_M3[CH*NMODE];
__device__ float2 g_B2[CH*S*Q72];
__device__ float2 g_B1[CH*S2*MO];
__device__ float2 g_wp[4*WLAYER];      // repacked spectral weights
__device__ float  g_xoe[NOUT*48];
__device__ float  g_xie[NIN*48];
__device__ float  g_fy [NOUT*CH];
__device__ float  g_kin[96*RTOT];
__device__ float  g_k1 [512*RTOT];
__device__ float  g_k2 [256*RTOT];
__device__ float  g_k3 [CH*RTOT];
__device__ float  g_gv [CH*NIN];
__device__ float  g_p1 [256*NIN];
__device__ double g_stats[2];
__device__ float  d_c12[648], d_s12[648];   // [p][t], p: freq 0..5,48..53
__device__ int    g_mask_fmt;               // 0=u8 1=i32 2=f32 3=bf16 4=i64

__device__ __forceinline__ float gelu_f(float x){
    return 0.5f*x*(1.0f+erff(x*0.7071067811865476f));
}

// ---------------- mask dtype detection ---------------------------------------
// nb_mask is 0/1 valued; dtype unknown (bool may be promoted by the harness).
// Byte signatures over the first 4096 bytes uniquely identify the dtype.
__global__ void detect_mask_k(const unsigned char* __restrict__ m){
    __shared__ int s_f1, s_f3, s_nzna, s_oddw;
    if(threadIdx.x==0){ s_f1=0; s_f3=0; s_nzna=0; s_oddw=0; }
    __syncthreads();
    for(int i=threadIdx.x; i<4096; i+=blockDim.x){
        unsigned char b = m[i];
        int off = i & 3;
        if(b){
            if(off==1 && b==0x3F) atomicOr(&s_f1, 1);        // bf16 1.0 = 0x3F80
            if(off==3 && b==0x3F) atomicOr(&s_f3, 1);        // f32 1.0f high byte
            if(off!=0)            atomicOr(&s_nzna, 1);
        }
    }
    // odd 32-bit words nonzero? (distinguish i32 from i64)
    const unsigned int* w = (const unsigned int*)m;
    for(int i=threadIdx.x; i<1024; i+=blockDim.x){
        if((i & 1) && w[i]) atomicOr(&s_oddw, 1);
    }
    __syncthreads();
    if(threadIdx.x==0){
        int fmt;
        if(s_f1)        fmt = 3;   // bf16
        else if(s_f3)   fmt = 2;   // f32
        else if(s_nzna) fmt = 0;   // u8/bool
        else if(s_oddw) fmt = 1;   // i32
        else            fmt = 4;   // i64
        g_mask_fmt = fmt;
    }
}

__device__ __forceinline__ int mask_at(const void* p, long r, int fmt){
    switch(fmt){
        case 0: return ((const unsigned char*)p)[r] != 0;
        case 1: return ((const int*)p)[r] != 0;
        case 2: return ((const float*)p)[r] != 0.f;
        case 3: return ((const unsigned short*)p)[r] != 0;
        default:return ((const long long*)p)[r] != 0;
    }
}

// ---------------- prep -------------------------------------------------------
__global__ void basis_k(){
    int t = blockIdx.x*blockDim.x + threadIdx.x;
    if(t >= 648) return;
    int p = t/54, z = t%54;
    int ef = (p<6) ? p : (p+42);          // 0..5, 48..53
    int m = (ef*z) % 54;
    double th = 6.283185307179586476925286766559 * (double)m / 54.0;
    d_c12[t] = (float)cos(th);
    d_s12[t] = (float)sin(th);
}

__global__ void zero_stats_k(){ g_stats[0]=0.0; g_stats[1]=0.0; }

__global__ void zero_h_k(){
    long i = (long)blockIdx.x*blockDim.x + threadIdx.x;
    if(i < CS) g_h[i] = 0.f;
}

// repack spec weights: src [l][blk][i][o][216] -> dst [l][blk][216][i][o] as float2
__global__ void repack_k(const float* __restrict__ wr, const float* __restrict__ wi){
    long idx = (long)blockIdx.x*256 + threadIdx.x;
    if(idx >= 25560576L) return;
    long x = idx;
    int o = (int)(x%86); x/=86;
    int i = (int)(x%86); x/=86;
    int mloc = (int)(x%216); x/=216;
    long lb = x;                           // 0..15 (layer*4+blk)
    long src = ((lb*86 + i)*86 + o)*216 + mloc;
    g_wp[idx] = make_float2(wr[src], wi[src]);
}

// ---------------- lift -------------------------------------------------------
__global__ void lift_k(const float* __restrict__ df, const float* __restrict__ xout,
                       const float* __restrict__ w, const float* __restrict__ b){
    int n = blockIdx.x*256 + threadIdx.x;
    int c = blockIdx.y;
    if(n >= NOUT) return;
    float f0 = df[n], f1 = df[NOUT + n];
    float f2 = xout[n*3+0], f3 = xout[n*3+1], f4 = xout[n*3+2];
    const float* wr = &w[c*5];
    float v = b[c] + wr[0]*f0 + wr[1]*f1 + wr[2]*f2 + wr[3]*f3 + wr[4]*f4;
    int i = n/2304, j = (n/48)%48, k = n%48;
    g_h[((size_t)(c*S + i)*S + j)*S + k] = v;
}

// ---------------- generic SGEMM: C[M,N] = act(W[M,K] @ X[K,N] + bias[M]) -----
template<int ACT>
__global__ __launch_bounds__(256) void sgemm_k(
    const float* __restrict__ W, const float* __restrict__ X,
    const float* __restrict__ B, float* __restrict__ C,
    int M, int K, int N)
{
    __shared__ float As[16][128];   // [k][m]
    __shared__ float Bs[16][64];    // [k][n]
    int bm = blockIdx.y*128, bn = blockIdx.x*64;
    int tid = threadIdx.x;
    int tm = (tid/16)*8;
    int tn = (tid%16)*4;
    float acc[8][4];
    #pragma unroll
    for(int i=0;i<8;i++)
        #pragma unroll
        for(int j=0;j<4;j++) acc[i][j]=0.f;

    for(int k0=0;k0<K;k0+=16){
        int ml = tid>>1, kb = (tid&1)*8;
        int gm = bm + ml;
        #pragma unroll
        for(int u=0;u<8;u++){
            int gk = k0 + kb + u;
            As[kb+u][ml] = (gm<M && gk<K) ? W[(size_t)gm*K + gk] : 0.f;
        }
        int kl = tid>>4, nb_ = (tid&15)*4;
        int gk = k0 + kl;
        #pragma unroll
        for(int u=0;u<4;u++){
            int gn = bn + nb_ + u;
            Bs[kl][nb_+u] = (gk<K && gn<N) ? X[(size_t)gk*N + gn] : 0.f;
        }
        __syncthreads();
        #pragma unroll
        for(int kk=0;kk<16;kk++){
            float4 a0 = *(const float4*)&As[kk][tm];
            float4 a1 = *(const float4*)&As[kk][tm+4];
            float4 bv = *(const float4*)&Bs[kk][tn];
            float a[8] = {a0.x,a0.y,a0.z,a0.w,a1.x,a1.y,a1.z,a1.w};
            float b[4] = {bv.x,bv.y,bv.z,bv.w};
            #pragma unroll
            for(int i=0;i<8;i++)
                #pragma unroll
                for(int j=0;j<4;j++) acc[i][j] = fmaf(a[i], b[j], acc[i][j]);
        }
        __syncthreads();
    }
    #pragma unroll
    for(int i=0;i<8;i++){
        int gm = bm + tm + i;
        if(gm >= M) continue;
        float bias = B ? B[gm] : 0.f;
        #pragma unroll
        for(int j=0;j<4;j++){
            int gn = bn + tn + j;
            if(gn < N){
                float v = acc[i][j] + bias;
                if(ACT) v = gelu_f(v);
                C[(size_t)gm*N + gn] = v;
            }
        }
    }
}

// ---------------- partial DFT chain -----------------------------------------
// forward z: rows = CH*S2, input h[row*54+z] -> A1[row*6+kz]
__global__ void dft_z_k(const float* __restrict__ h){
    __shared__ float sh[32*54];
    __shared__ float bc[324], bs[324];
    int t = threadIdx.x;                // 192
    long rowbase = (long)blockIdx.x*32;
    for(int i=t;i<324;i+=192){ bc[i]=d_c12[i]; bs[i]=d_s12[i]; }
    long gbase = rowbase*54;
    const long TOT = (long)CH*S2*54;
    for(int i=t;i<32*54;i+=192){
        long g = gbase + i;
        sh[i] = (g < TOT) ? h[g] : 0.f;
    }
    __syncthreads();
    int r = t/6, kz = t%6;
    long row = rowbase + r;
    if(row < (long)CH*S2){
        float re=0.f, im=0.f;
        const float* x = &sh[r*54];
        #pragma unroll
        for(int z=0;z<54;z++){
            float v = x[z];
            re = fmaf(v, bc[kz*54+z], re);
            im = fmaf(-v, bs[kz*54+z], im);
        }
        g_A1[row*6+kz] = make_float2(re, im);
    }
}

// forward y: per (c,x): [54y][6kz] -> [12ky][6kz]
__global__ void dft_y_k(){
    __shared__ float2 sh[324];
    int t = threadIdx.x;                // 128
    int cx = blockIdx.x;                // CH*S
    const float2* src = g_A1 + (size_t)cx*324;
    for(int i=t;i<324;i+=128) sh[i] = src[i];
    __syncthreads();
    if(t < 72){
        int ky = t/6, kz = t%6;
        float re=0.f, im=0.f;
        for(int y=0;y<54;y++){
            float2 v = sh[y*6+kz];
            float c = d_c12[ky*54+y], s = d_s12[ky*54+y];
            re += v.x*c + v.y*s;
            im += v.y*c - v.x*s;
        }
        g_A2[(size_t)cx*72 + t] = make_float2(re, im);
    }
}

// forward x: per c: [54x][72q] -> [12kx][72q]
__global__ void dft_x_k(){
    __shared__ float2 sh[S*Q72];
    int t = threadIdx.x;                // 256
    int c = blockIdx.x;
    const float2* src = g_A2 + (size_t)c*(S*Q72);
    for(int i=t;i<S*Q72;i+=256) sh[i] = src[i];
    __syncthreads();
    for(int u=t; u<NMODE; u+=256){
        int kx = u/72, q = u%72;
        float re=0.f, im=0.f;
        for(int x=0;x<54;x++){
            float2 v = sh[x*72+q];
            float c = d_c12[kx*54+x], s = d_s12[kx*54+x];
            re += v.x*c + v.y*s;
            im += v.y*c - v.x*s;
        }
        g_A3[(size_t)c*NMODE + u] = make_float2(re, im);
    }
}

// mode mixing: per mode m: out[o] = sum_i a[i] * W[blk][i][o][mloc]
__global__ void mix_k(const float2* __restrict__ wp){
    __shared__ float2 a[86];
    int m = blockIdx.x;                 // 864
    int t = threadIdx.x;                // 96
    int kx = m/72, ky = (m%72)/6, kz = m%6;
    if(t < 86) a[t] = g_A3[(size_t)t*NMODE + m];
    __syncthreads();
    if(t < 86){
        int cblk = (kx>=6)*2 + (ky>=6);
        int mloc = (kx%6)*36 + (ky%6)*6 + kz;
        const float2* w = wp + ((size_t)cblk*216 + mloc)*7396 + t;
        float re=0.f, im=0.f;
        for(int i=0;i<86;i++){
            float2 av = a[i];
            float2 wv = w[(size_t)i*86];
            re += av.x*wv.x - av.y*wv.y;
            im += av.x*wv.y + av.y*wv.x;
        }
        g_M3[(size_t)t*NMODE + m] = make_float2(re, im);
    }
}

// inverse x: per c: [12kx][72q] -> [54x][72q], e^{+i}
__global__ void inv_x_k(){
    __shared__ float2 sh[NMODE];
    int t = threadIdx.x;                // 256
    int c = blockIdx.x;
    for(int i=t;i<NMODE;i+=256) sh[i] = g_M3[(size_t)c*NMODE + i];
    __syncthreads();
    for(int u=t; u<S*Q72; u+=256){
        int x = u/72, q = u%72;
        float re=0.f, im=0.f;
        #pragma unroll
        for(int p=0;p<12;p++){
            float2 v = sh[p*72+q];
            float cc = d_c12[p*54+x], s = d_s12[p*54+x];
            re += v.x*cc - v.y*s;
            im += v.x*s  + v.y*cc;
        }
        g_B2[(size_t)c*(S*Q72) + u] = make_float2(re, im);
    }
}

// inverse y: per (c,x): [12ky][6kz] -> [54y][6kz]
__global__ void inv_y_k(){
    __shared__ float2 sh[72];
    int t = threadIdx.x;                // 128
    int cx = blockIdx.x;
    if(t < 72) sh[t] = g_B2[(size_t)cx*72 + t];
    __syncthreads();
    for(int u=t; u<324; u+=128){
        int y = u/6, kz = u%6;
        float re=0.f, im=0.f;
        #pragma unroll
        for(int ky=0;ky<12;ky++){
            float2 v = sh[ky*6+kz];
            float cc = d_c12[ky*54+y], s = d_s12[ky*54+y];
            re += v.x*cc - v.y*s;
            im += v.x*s  + v.y*cc;
        }
        g_B1[(size_t)cx*324 + u] = make_float2(re, im);
    }
}

// inverse z (to real, c2r semantics: imag of bin 0 ignored, bins 1..5 doubled)
__global__ void inv_z_k(){
    __shared__ float2 sh[324];
    int t = threadIdx.x;                // 256
    int cx = blockIdx.x;
    for(int i=t;i<324;i+=256) sh[i] = g_B1[(size_t)cx*324 + i];
    __syncthreads();
    const float inv = 1.0f/157464.0f;
    for(int u=t; u<S2; u+=256){
        int y = u/54, z = u%54;
        const float2* b = &sh[y*6];
        float v = b[0].x;
        #pragma unroll
        for(int kz=1;kz<6;kz++){
            float cc = d_c12[kz*54+z], s = d_s12[kz*54+z];
            v += 2.f*(b[kz].x*cc - b[kz].y*s);
        }
        g_hf[(size_t)cx*S2 + u] = v*inv;
    }
}

// ---------------- global group-norm stats + combine --------------------------
__global__ void reduce_stats_k(const float* __restrict__ x, int n){
    __shared__ double ss[256], ss2[256];
    double s=0.0, s2=0.0;
    for(long i=(long)blockIdx.x*blockDim.x+threadIdx.x; i<n; i+=(long)gridDim.x*blockDim.x){
        double v = x[i]; s += v; s2 += v*v;
    }
    ss[threadIdx.x]=s; ss2[threadIdx.x]=s2; __syncthreads();
    for(int o=128;o>0;o>>=1){
        if(threadIdx.x<o){ ss[threadIdx.x]+=ss[threadIdx.x+o]; ss2[threadIdx.x]+=ss2[threadIdx.x+o]; }
        __syncthreads();
    }
    if(threadIdx.x==0){ atomicAdd(&g_stats[0], ss[0]); atomicAdd(&g_stats[1], ss2[0]); }
}

// h = act( ((buf - mu)*rs)*gw[c] + gb[c] + add )
__global__ void combine_k(const float* __restrict__ buf, const float* __restrict__ add,
                          const float* __restrict__ gw, const float* __restrict__ gb,
                          float* __restrict__ h, int actflag){
    long i = (long)blockIdx.x*blockDim.x + threadIdx.x;
    if(i >= CS) return;
    double mu  = g_stats[0]/(double)CS;
    double var = g_stats[1]/(double)CS - mu*mu;
    float rs = (float)rsqrt(var + EPSGN);
    float fmu = (float)mu;
    int c = (int)(i / S3);
    float v = (buf[i]-fmu)*rs*gw[c] + gb[c] + add[i];
    if(actflag) v = gelu_f(v);
    h[i] = v;
}

// ---------------- GNO head ----------------------------------------------------
__global__ void embed_k(const float* __restrict__ pts, float* __restrict__ out, int n){
    int i = blockIdx.x*blockDim.x + threadIdx.x;
    if(i >= n) return;
    #pragma unroll
    for(int d=0; d<3; d++){
        float x = pts[i*3+d];
        #pragma unroll
        for(int f=0; f<8; f++){
            float fr = powf(1e-4f, (float)f/8.0f);
            float a = x*fr;
            out[(size_t)i*48 + d*16 + f]     = cosf(a);
            out[(size_t)i*48 + d*16 + 8 + f] = sinf(a);
        }
    }
}

__global__ void crop_k(){
    int n = blockIdx.x*256 + threadIdx.x;
    int c = blockIdx.y;
    if(n >= NOUT) return;
    int i = n/2304, j = (n/48)%48, k = n%48;
    g_fy[(size_t)n*CH + c] = g_h[((size_t)(c*S + i)*S + j)*S + k];
}

__global__ void build_kin_k(const int* __restrict__ nb_idx){
    int r = blockIdx.x*256 + threadIdx.x;
    if(r >= RTOT) return;
    int i = r / KNB;
    int idx = nb_idx[r];
    const float* ye = &g_xoe[(size_t)idx*48];
    const float* qe = &g_xie[(size_t)i*48];
    #pragma unroll
    for(int f=0; f<48; f++) g_kin[(size_t)f*RTOT + r]      = ye[f];
    #pragma unroll
    for(int f=0; f<48; f++) g_kin[(size_t)(48+f)*RTOT + r] = qe[f];
}

__global__ void gno_reduce_k(const int* __restrict__ nb_idx, const void* __restrict__ nb_mask){
    int i = blockIdx.x;                 // NIN
    int c = threadIdx.x;                // 96 (86 active)
    __shared__ int sidx[KNB]; __shared__ int smask[KNB];
    if(c < KNB){
        int fmt = g_mask_fmt;
        sidx[c]  = nb_idx[i*KNB + c];
        smask[c] = mask_at(nb_mask, (long)i*KNB + c, fmt);
    }
    __syncthreads();
    if(c >= CH) return;
    float acc = 0.f; int cnt = 0;
    #pragma unroll
    for(int j=0; j<KNB; j++){
        if(smask[j]){
            cnt++;
            acc += g_k3[(size_t)c*RTOT + i*KNB + j] * g_fy[(size_t)sidx[j]*CH + c];
        }
    }
    float den = (float)(cnt > 1 ? cnt : 1);
    g_gv[(size_t)c*NIN + i] = acc/den;
}

__global__ void p2_k(const float* __restrict__ w, const float* __restrict__ b,
                     float* __restrict__ out){
    int i = blockIdx.x*256 + threadIdx.x;
    if(i >= NIN) return;
    float acc = b[0];
    #pragma unroll 8
    for(int f=0; f<256; f++) acc = fmaf(w[f], g_p1[(size_t)f*NIN + i], acc);
    out[i] = acc;
}

// ---------------- host orchestration -----------------------------------------
static void sgemm(const float* W, const float* X, const float* B, float* C,
                  int M, int K, int N, int act){
    dim3 grid((N+63)/64, (M+127)/128);
    if(act) sgemm_k<1><<<grid,256>>>(W,X,B,C,M,K,N);
    else    sgemm_k<0><<<grid,256>>>(W,X,B,C,M,K,N);
}

extern "C" void kernel_launch(void* const* d_in, const int* in_sizes, int n_in,
                              void* d_out, int out_size){
    const float* x_in   = (const float*)d_in[0];
    const float* x_out  = (const float*)d_in[1];
    const float* df     = (const float*)d_in[2];
    const int*   nb_idx = (const int*)  d_in[3];
    const void*  nb_mask= (const void*) d_in[4];
    const float* w_lift = (const float*)d_in[5];
    const float* b_lift = (const float*)d_in[6];
    const float* spec_wr= (const float*)d_in[7];
    const float* spec_wi= (const float*)d_in[8];
    const float* w_skip = (const float*)d_in[9];
    const float* b_skip = (const float*)d_in[10];
    const float* mlp1_w = (const float*)d_in[11];
    const float* mlp1_b = (const float*)d_in[12];
    const float* mlp2_w = (const float*)d_in[13];
    const float* mlp2_b = (const float*)d_in[14];
    const float* wms    = (const float*)d_in[15];
    const float* bms    = (const float*)d_in[16];
    const float* g1w    = (const float*)d_in[17];
    const float* g1b    = (const float*)d_in[18];
    const float* g2w    = (const float*)d_in[19];
    const float* g2b    = (const float*)d_in[20];
    const float* k1w    = (const float*)d_in[21];
    const float* k1b    = (const float*)d_in[22];
    const float* k2w    = (const float*)d_in[23];
    const float* k2b    = (const float*)d_in[24];
    const float* k3w    = (const float*)d_in[25];
    const float* k3b    = (const float*)d_in[26];
    const float* p1w    = (const float*)d_in[27];
    const float* p1b    = (const float*)d_in[28];
    const float* p2w    = (const float*)d_in[29];
    const float* p2b    = (const float*)d_in[30];
    float* out = (float*)d_out;

    // device pointers for generic GEMM
    float *ph, *pskip, *phf, *pt1, *pkin, *pk1, *pk2, *pk3, *pgv, *pp1;
    float2 *pwp;
    cudaGetSymbolAddress((void**)&ph,    g_h);
    cudaGetSymbolAddress((void**)&pskip, g_skip);
    cudaGetSymbolAddress((void**)&phf,   g_hf);
    cudaGetSymbolAddress((void**)&pt1,   g_t1);
    cudaGetSymbolAddress((void**)&pkin,  g_kin);
    cudaGetSymbolAddress((void**)&pk1,   g_k1);
    cudaGetSymbolAddress((void**)&pk2,   g_k2);
    cudaGetSymbolAddress((void**)&pk3,   g_k3);
    cudaGetSymbolAddress((void**)&pgv,   g_gv);
    cudaGetSymbolAddress((void**)&pp1,   g_p1);
    cudaGetSymbolAddress((void**)&pwp,   g_wp);

    // prep
    basis_k<<<2,384>>>();
    detect_mask_k<<<1,256>>>((const unsigned char*)nb_mask);
    repack_k<<<(int)((25560576L+255)/256),256>>>(spec_wr, spec_wi);
    zero_h_k<<<(CS+255)/256,256>>>();
    {
        dim3 g((NOUT+255)/256, CH);
        lift_k<<<g,256>>>(df, x_out, w_lift, b_lift);
    }

    // FNO layers
    for(int l=0;l<4;l++){
        int act = (l<3) ? 1 : 0;
        // skip
        sgemm(w_skip + (size_t)l*CH*CH, ph, b_skip + l*CH, pskip, CH, CH, S3, 0);
        // spectral conv
        dft_z_k<<<(CH*S2+31)/32, 192>>>(ph);
        dft_y_k<<<CH*S, 128>>>();
        dft_x_k<<<CH, 256>>>();
        mix_k<<<NMODE, 96>>>(pwp + (size_t)l*WLAYER);
        inv_x_k<<<CH, 256>>>();
        inv_y_k<<<CH*S, 128>>>();
        inv_z_k<<<CH*S, 256>>>();
        // group norm 1 + skip + act
        zero_stats_k<<<1,1>>>();
        reduce_stats_k<<<2048,256>>>(phf, CS);
        combine_k<<<(CS+255)/256,256>>>(phf, pskip, g1w + l*CH, g1b + l*CH, ph, act);
        // mlp block
        sgemm(wms    + (size_t)l*CH*CH, ph,  bms    + l*CH, pskip, CH, CH, S3, 0); // mskip
        sgemm(mlp1_w + (size_t)l*CH*CH, ph,  mlp1_b + l*CH, pt1,   CH, CH, S3, 1);
        sgemm(mlp2_w + (size_t)l*CH*CH, pt1, mlp2_b + l*CH, phf,   CH, CH, S3, 0);
        zero_stats_k<<<1,1>>>();
        reduce_stats_k<<<2048,256>>>(phf, CS);
        combine_k<<<(CS+255)/256,256>>>(phf, pskip, g2w + l*CH, g2b + l*CH, ph, act);
    }

    // crop f_y
    {
        dim3 g((NOUT+255)/256, CH);
        crop_k<<<g,256>>>();
    }

    // embeddings
    {
        float *pxoe, *pxie;
        cudaGetSymbolAddress((void**)&pxoe, g_xoe);
        cudaGetSymbolAddress((void**)&pxie, g_xie);
        embed_k<<<(NOUT+127)/128,128>>>(x_out, pxoe, NOUT);
        embed_k<<<(NIN +127)/128,128>>>(x_in,  pxie, NIN);
    }

    // GNO kernel MLP
    build_kin_k<<<(RTOT+255)/256,256>>>(nb_idx);
    sgemm(k1w, pkin, k1b, pk1, 512,  96, RTOT, 1);
    sgemm(k2w, pk1,  k2b, pk2, 256, 512, RTOT, 1);
    sgemm(k3w, pk2,  k3b, pk3,  CH, 256, RTOT, 0);

    // masked neighbor reduce
    gno_reduce_k<<<NIN, 96>>>(nb_idx, nb_mask);

    // projection MLP
    sgemm(p1w, pgv, p1b, pp1, 256, CH, NIN, 1);
    p2_k<<<(NIN+255)/256,256>>>(p2w, p2b, out);
}

// round 3
// speedup vs baseline: 1.6873x; 1.6873x over previous
#include <cuda_runtime.h>
#include <cuda_bf16.h>
#include <math.h>

// ----------------------------------------------------------------------------
// FNO-GNO forward, sm_103a. fp32. Partial separable DFT spectral conv.
// Round 3: 128x128 double-buffered SGEMM, k1 decomposition, fp32 stats.
// ----------------------------------------------------------------------------

#define S 54
#define S2 2916
#define S3 157464
#define CH 86
#define CS 13541904        // 86 * S3
#define NOUT 110592        // 48^3
#define NIN 8192
#define KNB 24
#define RTOT 196608        // NIN*KNB
#define MO 6
#define Q72 72
#define NMODE 864
#define WLAYER 6390144     // 4*216*86*86 (float2 per layer)
#define EPSGN 1e-5

// ---------------- device scratch ---------------------------------------------
__device__ float  g_h   [CS];
__device__ float  g_skip[CS];
__device__ float  g_hf  [CS];
__device__ float  g_t1  [CS];
__device__ float2 g_A1[CH*S2*MO];
__device__ float2 g_A2[CH*S*Q72];
__device__ float2 g_A3[CH*NMODE];
__device__ float2 g_M3[CH*NMODE];
__device__ float2 g_B2[CH*S*Q72];
__device__ float2 g_B1[CH*S2*MO];
__device__ float2 g_wp[4*WLAYER];
__device__ float  g_xoe[48*NOUT];       // transposed [f][n]
__device__ float  g_xie[48*NIN];        // transposed [f][n]
__device__ float  g_fy [NOUT*CH];
__device__ float  g_y1 [512*(size_t)NOUT];
__device__ float  g_q1 [512*NIN];
__device__ float  g_k1 [512*(size_t)RTOT];
__device__ float  g_k2 [256*(size_t)RTOT];
__device__ float  g_k3 [CH*(size_t)RTOT];
__device__ float  g_gv [CH*NIN];
__device__ float  g_p1 [256*NIN];
__device__ double g_stats[2];
__device__ float  d_c12[648], d_s12[648];
__device__ int    g_mask_fmt;

__device__ __forceinline__ float gelu_f(float x){
    return 0.5f*x*(1.0f+erff(x*0.7071067811865476f));
}

// ---------------- mask dtype detection ---------------------------------------
__global__ void detect_mask_k(const unsigned char* __restrict__ m){
    __shared__ int s_f1, s_f3, s_nzna, s_oddw;
    if(threadIdx.x==0){ s_f1=0; s_f3=0; s_nzna=0; s_oddw=0; }
    __syncthreads();
    for(int i=threadIdx.x; i<4096; i+=blockDim.x){
        unsigned char b = m[i];
        int off = i & 3;
        if(b){
            if(off==1 && b==0x3F) atomicOr(&s_f1, 1);
            if(off==3 && b==0x3F) atomicOr(&s_f3, 1);
            if(off!=0)            atomicOr(&s_nzna, 1);
        }
    }
    const unsigned int* w = (const unsigned int*)m;
    for(int i=threadIdx.x; i<1024; i+=blockDim.x){
        if((i & 1) && w[i]) atomicOr(&s_oddw, 1);
    }
    __syncthreads();
    if(threadIdx.x==0){
        int fmt;
        if(s_f1)        fmt = 3;
        else if(s_f3)   fmt = 2;
        else if(s_nzna) fmt = 0;
        else if(s_oddw) fmt = 1;
        else            fmt = 4;
        g_mask_fmt = fmt;
    }
}

__device__ __forceinline__ int mask_at(const void* p, long r, int fmt){
    switch(fmt){
        case 0: return ((const unsigned char*)p)[r] != 0;
        case 1: return ((const int*)p)[r] != 0;
        case 2: return ((const float*)p)[r] != 0.f;
        case 3: return ((const unsigned short*)p)[r] != 0;
        default:return ((const long long*)p)[r] != 0;
    }
}

// ---------------- prep -------------------------------------------------------
__global__ void basis_k(){
    int t = blockIdx.x*blockDim.x + threadIdx.x;
    if(t >= 648) return;
    int p = t/54, z = t%54;
    int ef = (p<6) ? p : (p+42);
    int m = (ef*z) % 54;
    double th = 6.283185307179586476925286766559 * (double)m / 54.0;
    d_c12[t] = (float)cos(th);
    d_s12[t] = (float)sin(th);
}

__global__ void zero_stats_k(){ g_stats[0]=0.0; g_stats[1]=0.0; }

__global__ void zero_h_k(){
    long i = (long)blockIdx.x*blockDim.x + threadIdx.x;
    if(i < CS) g_h[i] = 0.f;
}

__global__ void repack_k(const float* __restrict__ wr, const float* __restrict__ wi){
    long idx = (long)blockIdx.x*256 + threadIdx.x;
    if(idx >= 25560576L) return;
    long x = idx;
    int o = (int)(x%86); x/=86;
    int i = (int)(x%86); x/=86;
    int mloc = (int)(x%216); x/=216;
    long lb = x;
    long src = ((lb*86 + i)*86 + o)*216 + mloc;
    g_wp[idx] = make_float2(wr[src], wi[src]);
}

// ---------------- lift -------------------------------------------------------
__global__ void lift_k(const float* __restrict__ df, const float* __restrict__ xout,
                       const float* __restrict__ w, const float* __restrict__ b){
    int n = blockIdx.x*256 + threadIdx.x;
    int c = blockIdx.y;
    if(n >= NOUT) return;
    float f0 = df[n], f1 = df[NOUT + n];
    float f2 = xout[n*3+0], f3 = xout[n*3+1], f4 = xout[n*3+2];
    const float* wr = &w[c*5];
    float v = b[c] + wr[0]*f0 + wr[1]*f1 + wr[2]*f2 + wr[3]*f3 + wr[4]*f4;
    int i = n/2304, j = (n/48)%48, k = n%48;
    g_h[((size_t)(c*S + i)*S + j)*S + k] = v;
}

// ---------------- SGEMM 128x128x8, double-buffered ---------------------------
// C[M,N] = act(W[M,*lda] @ X[K,N] + bias[M]),  W row m uses k = 0..K-1
template<int ACT>
__global__ __launch_bounds__(256, 2) void sgemm128_k(
    const float* __restrict__ W, int lda,
    const float* __restrict__ X,
    const float* __restrict__ Bv, float* __restrict__ C,
    int M, int K, int N)
{
    __shared__ float As[2][8][128];
    __shared__ float Bs[2][8][128];
    const int bm = blockIdx.y*128, bn = blockIdx.x*128;
    const int tid = threadIdx.x;
    const int tx = tid & 15, ty = tid >> 4;
    const int row0 = ty*8, col0 = tx*8;
    const int b_r = tid >> 5, b_c = (tid & 31)*4;

    float acc[8][8];
    #pragma unroll
    for(int i=0;i<8;i++)
        #pragma unroll
        for(int j=0;j<8;j++) acc[i][j]=0.f;

    float a_reg[4];
    float4 b_reg;

    auto loadT = [&](int kt){
        #pragma unroll
        for(int u=0;u<4;u++){
            int idx = tid + u*256;
            int m = idx & 127, k = idx >> 7;
            int gm = bm + m, gk = kt*8 + k;
            a_reg[u] = (gm < M && gk < K) ? W[(size_t)gm*lda + gk] : 0.f;
        }
        int gk = kt*8 + b_r, gn = bn + b_c;
        if(gk < K && gn + 3 < N){
            b_reg = *(const float4*)&X[(size_t)gk*N + gn];
        } else {
            b_reg.x = (gk<K && gn+0<N) ? X[(size_t)gk*N + gn+0] : 0.f;
            b_reg.y = (gk<K && gn+1<N) ? X[(size_t)gk*N + gn+1] : 0.f;
            b_reg.z = (gk<K && gn+2<N) ? X[(size_t)gk*N + gn+2] : 0.f;
            b_reg.w = (gk<K && gn+3<N) ? X[(size_t)gk*N + gn+3] : 0.f;
        }
    };
    auto storeT = [&](int b){
        #pragma unroll
        for(int u=0;u<4;u++){
            int idx = tid + u*256;
            As[b][idx>>7][idx&127] = a_reg[u];
        }
        *(float4*)&Bs[b][b_r][b_c] = b_reg;
    };
    auto comp = [&](int b){
        #pragma unroll
        for(int kk=0;kk<8;kk++){
            float4 a0 = *(const float4*)&As[b][kk][row0];
            float4 a1 = *(const float4*)&As[b][kk][row0+4];
            float4 c0 = *(const float4*)&Bs[b][kk][col0];
            float4 c1 = *(const float4*)&Bs[b][kk][col0+4];
            float af[8]={a0.x,a0.y,a0.z,a0.w,a1.x,a1.y,a1.z,a1.w};
            float bf[8]={c0.x,c0.y,c0.z,c0.w,c1.x,c1.y,c1.z,c1.w};
            #pragma unroll
            for(int i=0;i<8;i++)
                #pragma unroll
                for(int j=0;j<8;j++)
                    acc[i][j] = fmaf(af[i], bf[j], acc[i][j]);
        }
    };

    int ntiles = (K+7)>>3;
    loadT(0); storeT(0);
    __syncthreads();
    int buf = 0;
    for(int t=1; t<ntiles; t++){
        loadT(t);
        comp(buf);
        storeT(buf^1);
        __syncthreads();
        buf ^= 1;
    }
    comp(buf);

    #pragma unroll
    for(int i=0;i<8;i++){
        int gm = bm + row0 + i;
        if(gm >= M) continue;
        float bias = Bv ? Bv[gm] : 0.f;
        #pragma unroll
        for(int j=0;j<8;j+=4){
            int gn = bn + col0 + j;
            float v0 = acc[i][j+0] + bias;
            float v1 = acc[i][j+1] + bias;
            float v2 = acc[i][j+2] + bias;
            float v3 = acc[i][j+3] + bias;
            if(ACT){ v0=gelu_f(v0); v1=gelu_f(v1); v2=gelu_f(v2); v3=gelu_f(v3); }
            if(gn + 3 < N){
                float4 o = make_float4(v0,v1,v2,v3);
                *(float4*)&C[(size_t)gm*N + gn] = o;
            } else {
                if(gn+0<N) C[(size_t)gm*N + gn+0] = v0;
                if(gn+1<N) C[(size_t)gm*N + gn+1] = v1;
                if(gn+2<N) C[(size_t)gm*N + gn+2] = v2;
                if(gn+3<N) C[(size_t)gm*N + gn+3] = v3;
            }
        }
    }
}

// ---------------- partial DFT chain -----------------------------------------
__global__ void dft_z_k(const float* __restrict__ h){
    __shared__ float sh[32*54];
    __shared__ float bc[324], bs[324];
    int t = threadIdx.x;                // 192
    long rowbase = (long)blockIdx.x*32;
    for(int i=t;i<324;i+=192){ bc[i]=d_c12[i]; bs[i]=d_s12[i]; }
    long gbase = rowbase*54;
    const long TOT = (long)CH*S2*54;
    for(int i=t;i<32*54;i+=192){
        long g = gbase + i;
        sh[i] = (g < TOT) ? h[g] : 0.f;
    }
    __syncthreads();
    int r = t/6, kz = t%6;
    long row = rowbase + r;
    if(row < (long)CH*S2){
        float re=0.f, im=0.f;
        const float* x = &sh[r*54];
        #pragma unroll
        for(int z=0;z<54;z++){
            float v = x[z];
            re = fmaf(v, bc[kz*54+z], re);
            im = fmaf(-v, bs[kz*54+z], im);
        }
        g_A1[row*6+kz] = make_float2(re, im);
    }
}

__global__ void dft_y_k(){
    __shared__ float2 sh[324];
    int t = threadIdx.x;                // 128
    int cx = blockIdx.x;
    const float2* src = g_A1 + (size_t)cx*324;
    for(int i=t;i<324;i+=128) sh[i] = src[i];
    __syncthreads();
    if(t < 72){
        int ky = t/6, kz = t%6;
        float re=0.f, im=0.f;
        for(int y=0;y<54;y++){
            float2 v = sh[y*6+kz];
            float c = d_c12[ky*54+y], s = d_s12[ky*54+y];
            re += v.x*c + v.y*s;
            im += v.y*c - v.x*s;
        }
        g_A2[(size_t)cx*72 + t] = make_float2(re, im);
    }
}

__global__ void dft_x_k(){
    __shared__ float2 sh[S*Q72];
    int t = threadIdx.x;                // 256
    int c = blockIdx.x;
    const float2* src = g_A2 + (size_t)c*(S*Q72);
    for(int i=t;i<S*Q72;i+=256) sh[i] = src[i];
    __syncthreads();
    for(int u=t; u<NMODE; u+=256){
        int kx = u/72, q = u%72;
        float re=0.f, im=0.f;
        for(int x=0;x<54;x++){
            float2 v = sh[x*72+q];
            float c = d_c12[kx*54+x], s = d_s12[kx*54+x];
            re += v.x*c + v.y*s;
            im += v.y*c - v.x*s;
        }
        g_A3[(size_t)c*NMODE + u] = make_float2(re, im);
    }
}

__global__ void mix_k(const float2* __restrict__ wp){
    __shared__ float2 a[86];
    int m = blockIdx.x;                 // 864
    int t = threadIdx.x;                // 96
    int kx = m/72, ky = (m%72)/6, kz = m%6;
    if(t < 86) a[t] = g_A3[(size_t)t*NMODE + m];
    __syncthreads();
    if(t < 86){
        int cblk = (kx>=6)*2 + (ky>=6);
        int mloc = (kx%6)*36 + (ky%6)*6 + kz;
        const float2* w = wp + ((size_t)cblk*216 + mloc)*7396 + t;
        float re=0.f, im=0.f;
        for(int i=0;i<86;i++){
            float2 av = a[i];
            float2 wv = w[(size_t)i*86];
            re += av.x*wv.x - av.y*wv.y;
            im += av.x*wv.y + av.y*wv.x;
        }
        g_M3[(size_t)t*NMODE + m] = make_float2(re, im);
    }
}

__global__ void inv_x_k(){
    __shared__ float2 sh[NMODE];
    int t = threadIdx.x;                // 256
    int c = blockIdx.x;
    for(int i=t;i<NMODE;i+=256) sh[i] = g_M3[(size_t)c*NMODE + i];
    __syncthreads();
    for(int u=t; u<S*Q72; u+=256){
        int x = u/72, q = u%72;
        float re=0.f, im=0.f;
        #pragma unroll
        for(int p=0;p<12;p++){
            float2 v = sh[p*72+q];
            float cc = d_c12[p*54+x], s = d_s12[p*54+x];
            re += v.x*cc - v.y*s;
            im += v.x*s  + v.y*cc;
        }
        g_B2[(size_t)c*(S*Q72) + u] = make_float2(re, im);
    }
}

__global__ void inv_y_k(){
    __shared__ float2 sh[72];
    int t = threadIdx.x;                // 128
    int cx = blockIdx.x;
    if(t < 72) sh[t] = g_B2[(size_t)cx*72 + t];
    __syncthreads();
    for(int u=t; u<324; u+=128){
        int y = u/6, kz = u%6;
        float re=0.f, im=0.f;
        #pragma unroll
        for(int ky=0;ky<12;ky++){
            float2 v = sh[ky*6+kz];
            float cc = d_c12[ky*54+y], s = d_s12[ky*54+y];
            re += v.x*cc - v.y*s;
            im += v.x*s  + v.y*cc;
        }
        g_B1[(size_t)cx*324 + u] = make_float2(re, im);
    }
}

__global__ void inv_z_k(){
    __shared__ float2 sh[324];
    int t = threadIdx.x;                // 256
    int cx = blockIdx.x;
    for(int i=t;i<324;i+=256) sh[i] = g_B1[(size_t)cx*324 + i];
    __syncthreads();
    const float inv = 1.0f/157464.0f;
    for(int u=t; u<S2; u+=256){
        int y = u/54, z = u%54;
        const float2* b = &sh[y*6];
        float v = b[0].x;
        #pragma unroll
        for(int kz=1;kz<6;kz++){
            float cc = d_c12[kz*54+z], s = d_s12[kz*54+z];
            v += 2.f*(b[kz].x*cc - b[kz].y*s);
        }
        g_hf[(size_t)cx*S2 + u] = v*inv;
    }
}

// ---------------- group-norm stats + combine ----------------------------------
__global__ void reduce_stats_k(const float* __restrict__ x, int n){
    const float4* x4 = (const float4*)x;
    int n4 = n >> 2;
    float s=0.f, s2=0.f;
    for(long i=(long)blockIdx.x*blockDim.x+threadIdx.x; i<n4; i+=(long)gridDim.x*blockDim.x){
        float4 v = x4[i];
        s += v.x+v.y+v.z+v.w;
        s2 = fmaf(v.x,v.x, fmaf(v.y,v.y, fmaf(v.z,v.z, fmaf(v.w,v.w, s2))));
    }
    #pragma unroll
    for(int o=16;o>0;o>>=1){
        s  += __shfl_down_sync(0xffffffffu, s, o);
        s2 += __shfl_down_sync(0xffffffffu, s2, o);
    }
    __shared__ double ds[8], ds2[8];
    int w = threadIdx.x>>5;
    if((threadIdx.x&31)==0){ ds[w]=(double)s; ds2[w]=(double)s2; }
    __syncthreads();
    if(threadIdx.x==0){
        double a=0,b=0;
        #pragma unroll
        for(int k=0;k<8;k++){ a+=ds[k]; b+=ds2[k]; }
        atomicAdd(&g_stats[0], a);
        atomicAdd(&g_stats[1], b);
    }
}

__global__ void combine_k(const float4* __restrict__ buf, const float4* __restrict__ add,
                          const float* __restrict__ gw, const float* __restrict__ gb,
                          float4* __restrict__ h, int actflag){
    long i = (long)blockIdx.x*blockDim.x + threadIdx.x;
    if(i >= (CS>>2)) return;
    double mu  = g_stats[0]/(double)CS;
    double var = g_stats[1]/(double)CS - mu*mu;
    float rs = (float)rsqrt(var + EPSGN);
    float fmu = (float)mu;
    int c = (int)((i<<2) / S3);
    float sw = rs*gw[c], sb = gb[c];
    float4 u = buf[i], a = add[i];
    float4 o;
    o.x = (u.x-fmu)*sw + sb + a.x;
    o.y = (u.y-fmu)*sw + sb + a.y;
    o.z = (u.z-fmu)*sw + sb + a.z;
    o.w = (u.w-fmu)*sw + sb + a.w;
    if(actflag){ o.x=gelu_f(o.x); o.y=gelu_f(o.y); o.z=gelu_f(o.z); o.w=gelu_f(o.w); }
    h[i] = o;
}

// ---------------- GNO head ----------------------------------------------------
// transposed embed: out[f][n]
__global__ void embed_t_k(const float* __restrict__ pts, float* __restrict__ out, int n){
    int i = blockIdx.x*blockDim.x + threadIdx.x;
    if(i >= n) return;
    #pragma unroll
    for(int d=0; d<3; d++){
        float x = pts[i*3+d];
        #pragma unroll
        for(int f=0; f<8; f++){
            float fr = powf(1e-4f, (float)f/8.0f);
            float a = x*fr;
            out[(size_t)(d*16+f)*n + i]     = cosf(a);
            out[(size_t)(d*16+8+f)*n + i]   = sinf(a);
        }
    }
}

__global__ void crop_k(){
    int n = blockIdx.x*256 + threadIdx.x;
    int c = blockIdx.y;
    if(n >= NOUT) return;
    int i = n/2304, j = (n/48)%48, k = n%48;
    g_fy[(size_t)n*CH + c] = g_h[((size_t)(c*S + i)*S + j)*S + k];
}

// k1[o][r] = gelu( Y1[o][nb_idx[r]] + Q1[o][r/24] )   (bias folded into Q1)
__global__ void k1_fuse_k(const int* __restrict__ nb_idx){
    int r = blockIdx.x*256 + threadIdx.x;
    int idx = nb_idx[r];
    int i = r / KNB;
    const float* y = g_y1 + idx;
    const float* q = g_q1 + i;
    float* o = g_k1 + r;
    #pragma unroll 4
    for(int c=0; c<512; c++){
        float v = y[(size_t)c*NOUT] + q[(size_t)c*NIN];
        o[(size_t)c*RTOT] = gelu_f(v);
    }
}

__global__ void gno_reduce_k(const int* __restrict__ nb_idx, const void* __restrict__ nb_mask){
    int i = blockIdx.x;                 // NIN
    int c = threadIdx.x;                // 96 (86 active)
    __shared__ int sidx[KNB]; __shared__ int smask[KNB];
    if(c < KNB){
        int fmt = g_mask_fmt;
        sidx[c]  = nb_idx[i*KNB + c];
        smask[c] = mask_at(nb_mask, (long)i*KNB + c, fmt);
    }
    __syncthreads();
    if(c >= CH) return;
    float acc = 0.f; int cnt = 0;
    #pragma unroll
    for(int j=0; j<KNB; j++){
        if(smask[j]){
            cnt++;
            acc += g_k3[(size_t)c*RTOT + i*KNB + j] * g_fy[(size_t)sidx[j]*CH + c];
        }
    }
    float den = (float)(cnt > 1 ? cnt : 1);
    g_gv[(size_t)c*NIN + i] = acc/den;
}

__global__ void p2_k(const float* __restrict__ w, const float* __restrict__ b,
                     float* __restrict__ out){
    int i = blockIdx.x*256 + threadIdx.x;
    if(i >= NIN) return;
    float acc = b[0];
    #pragma unroll 8
    for(int f=0; f<256; f++) acc = fmaf(w[f], g_p1[(size_t)f*NIN + i], acc);
    out[i] = acc;
}

// ---------------- host orchestration -----------------------------------------
static void sgemm(const float* W, int lda, const float* X, const float* B, float* C,
                  int M, int K, int N, int act){
    dim3 grid((N+127)/128, (M+127)/128);
    if(act) sgemm128_k<1><<<grid,256>>>(W,lda,X,B,C,M,K,N);
    else    sgemm128_k<0><<<grid,256>>>(W,lda,X,B,C,M,K,N);
}

extern "C" void kernel_launch(void* const* d_in, const int* in_sizes, int n_in,
                              void* d_out, int out_size){
    const float* x_in   = (const float*)d_in[0];
    const float* x_out  = (const float*)d_in[1];
    const float* df     = (const float*)d_in[2];
    const int*   nb_idx = (const int*)  d_in[3];
    const void*  nb_mask= (const void*) d_in[4];
    const float* w_lift = (const float*)d_in[5];
    const float* b_lift = (const float*)d_in[6];
    const float* spec_wr= (const float*)d_in[7];
    const float* spec_wi= (const float*)d_in[8];
    const float* w_skip = (const float*)d_in[9];
    const float* b_skip = (const float*)d_in[10];
    const float* mlp1_w = (const float*)d_in[11];
    const float* mlp1_b = (const float*)d_in[12];
    const float* mlp2_w = (const float*)d_in[13];
    const float* mlp2_b = (const float*)d_in[14];
    const float* wms    = (const float*)d_in[15];
    const float* bms    = (const float*)d_in[16];
    const float* g1w    = (const float*)d_in[17];
    const float* g1b    = (const float*)d_in[18];
    const float* g2w    = (const float*)d_in[19];
    const float* g2b    = (const float*)d_in[20];
    const float* k1w    = (const float*)d_in[21];
    const float* k1b    = (const float*)d_in[22];
    const float* k2w    = (const float*)d_in[23];
    const float* k2b    = (const float*)d_in[24];
    const float* k3w    = (const float*)d_in[25];
    const float* k3b    = (const float*)d_in[26];
    const float* p1w    = (const float*)d_in[27];
    const float* p1b    = (const float*)d_in[28];
    const float* p2w    = (const float*)d_in[29];
    const float* p2b    = (const float*)d_in[30];
    float* out = (float*)d_out;

    float *ph, *pskip, *phf, *pt1, *pxoe, *pxie, *py1, *pq1, *pk1, *pk2, *pk3, *pgv, *pp1;
    float2 *pwp;
    cudaGetSymbolAddress((void**)&ph,    g_h);
    cudaGetSymbolAddress((void**)&pskip, g_skip);
    cudaGetSymbolAddress((void**)&phf,   g_hf);
    cudaGetSymbolAddress((void**)&pt1,   g_t1);
    cudaGetSymbolAddress((void**)&pxoe,  g_xoe);
    cudaGetSymbolAddress((void**)&pxie,  g_xie);
    cudaGetSymbolAddress((void**)&py1,   g_y1);
    cudaGetSymbolAddress((void**)&pq1,   g_q1);
    cudaGetSymbolAddress((void**)&pk1,   g_k1);
    cudaGetSymbolAddress((void**)&pk2,   g_k2);
    cudaGetSymbolAddress((void**)&pk3,   g_k3);
    cudaGetSymbolAddress((void**)&pgv,   g_gv);
    cudaGetSymbolAddress((void**)&pp1,   g_p1);
    cudaGetSymbolAddress((void**)&pwp,   g_wp);

    // prep
    basis_k<<<2,384>>>();
    detect_mask_k<<<1,256>>>((const unsigned char*)nb_mask);
    repack_k<<<(int)((25560576L+255)/256),256>>>(spec_wr, spec_wi);
    zero_h_k<<<(CS+255)/256,256>>>();
    {
        dim3 g((NOUT+255)/256, CH);
        lift_k<<<g,256>>>(df, x_out, w_lift, b_lift);
    }

    // FNO layers
    for(int l=0;l<4;l++){
        int act = (l<3) ? 1 : 0;
        sgemm(w_skip + (size_t)l*CH*CH, CH, ph, b_skip + l*CH, pskip, CH, CH, S3, 0);
        dft_z_k<<<(CH*S2+31)/32, 192>>>(ph);
        dft_y_k<<<CH*S, 128>>>();
        dft_x_k<<<CH, 256>>>();
        mix_k<<<NMODE, 96>>>(pwp + (size_t)l*WLAYER);
        inv_x_k<<<CH, 256>>>();
        inv_y_k<<<CH*S, 128>>>();
        inv_z_k<<<CH*S, 256>>>();
        zero_stats_k<<<1,1>>>();
        reduce_stats_k<<<2048,256>>>(phf, CS);
        combine_k<<<((CS>>2)+255)/256,256>>>((const float4*)phf,(const float4*)pskip,
                                             g1w + l*CH, g1b + l*CH, (float4*)ph, act);
        sgemm(wms    + (size_t)l*CH*CH, CH, ph,  bms    + l*CH, pskip, CH, CH, S3, 0);
        sgemm(mlp1_w + (size_t)l*CH*CH, CH, ph,  mlp1_b + l*CH, pt1,   CH, CH, S3, 1);
        sgemm(mlp2_w + (size_t)l*CH*CH, CH, pt1, mlp2_b + l*CH, phf,   CH, CH, S3, 0);
        zero_stats_k<<<1,1>>>();
        reduce_stats_k<<<2048,256>>>(phf, CS);
        combine_k<<<((CS>>2)+255)/256,256>>>((const float4*)phf,(const float4*)pskip,
                                             g2w + l*CH, g2b + l*CH, (float4*)ph, act);
    }

    // crop f_y
    {
        dim3 g((NOUT+255)/256, CH);
        crop_k<<<g,256>>>();
    }

    // transposed embeddings
    embed_t_k<<<(NOUT+127)/128,128>>>(x_out, pxoe, NOUT);
    embed_t_k<<<(NIN +127)/128,128>>>(x_in,  pxie, NIN);

    // GNO kernel MLP: k1 split into Y1 (grid part) + Q1 (query part, bias folded)
    sgemm(k1w,      96, pxoe, 0,   py1, 512, 48, NOUT, 0);
    sgemm(k1w + 48, 96, pxie, k1b, pq1, 512, 48, NIN,  0);
    k1_fuse_k<<<RTOT/256,256>>>(nb_idx);
    sgemm(k2w, 512, pk1, k2b, pk2, 256, 512, RTOT, 1);
    sgemm(k3w, 256, pk2, k3b, pk3,  CH, 256, RTOT, 0);

    // masked neighbor reduce
    gno_reduce_k<<<NIN, 96>>>(nb_idx, nb_mask);

    // projection MLP
    sgemm(p1w, CH, pgv, p1b, pp1, 256, CH, NIN, 1);
    p2_k<<<(NIN+255)/256,256>>>(p2w, p2b, out);
}

// round 4
// speedup vs baseline: 1.8998x; 1.1259x over previous
#include <cuda_runtime.h>
#include <cuda_bf16.h>
#include <math.h>

// ----------------------------------------------------------------------------
// FNO-GNO forward, sm_103a. Round 4: all GEMMs on tensor pipe via
// mma.sync.m16n8k8.tf32 with 3xTF32 split (fp32-accurate). Partial separable
// DFT spectral conv (no cuFFT, no allocations).
// ----------------------------------------------------------------------------

#define S 54
#define S2 2916
#define S3 157464
#define CH 86
#define CS 13541904        // 86 * S3
#define NOUT 110592        // 48^3
#define NIN 8192
#define KNB 24
#define RTOT 196608        // NIN*KNB
#define MO 6
#define Q72 72
#define NMODE 864
#define WLAYER 6390144     // 4*216*86*86 (float2 per layer)
#define EPSGN 1e-5

// ---------------- device scratch ---------------------------------------------
__device__ float  g_h   [CS];
__device__ float  g_skip[CS];
__device__ float  g_hf  [CS];
__device__ float  g_t1  [CS];
__device__ float2 g_A1[CH*S2*MO];
__device__ float2 g_A2[CH*S*Q72];
__device__ float2 g_A3[CH*NMODE];
__device__ float2 g_M3[CH*NMODE];
__device__ float2 g_B2[CH*S*Q72];
__device__ float2 g_B1[CH*S2*MO];
__device__ float2 g_wp[4*WLAYER];
__device__ float  g_xoe[48*NOUT];       // transposed [f][n]
__device__ float  g_xie[48*NIN];        // transposed [f][n]
__device__ float  g_fy [NOUT*CH];
__device__ float  g_y1 [512*(size_t)NOUT];
__device__ float  g_q1 [512*NIN];
__device__ float  g_k1 [512*(size_t)RTOT];
__device__ float  g_k2 [256*(size_t)RTOT];
__device__ float  g_k3 [CH*(size_t)RTOT];
__device__ float  g_gv [CH*NIN];
__device__ float  g_p1 [256*NIN];
__device__ double g_stats[2];
__device__ float  d_c12[648], d_s12[648];
__device__ int    g_mask_fmt;

__device__ __forceinline__ float gelu_f(float x){
    return 0.5f*x*(1.0f+erff(x*0.7071067811865476f));
}

// ---------------- tf32 helpers ------------------------------------------------
__device__ __forceinline__ unsigned cvt_tf32(float x){
    unsigned r;
    asm("cvt.rna.tf32.f32 %0, %1;" : "=r"(r) : "f"(x));
    return r;
}

__device__ __forceinline__ void mma8(float* c,
        unsigned a0, unsigned a1, unsigned a2, unsigned a3,
        unsigned b0, unsigned b1){
    asm volatile(
        "mma.sync.aligned.m16n8k8.row.col.f32.tf32.tf32.f32 "
        "{%0,%1,%2,%3}, {%4,%5,%6,%7}, {%8,%9}, {%0,%1,%2,%3};"
        : "+f"(c[0]), "+f"(c[1]), "+f"(c[2]), "+f"(c[3])
        : "r"(a0), "r"(a1), "r"(a2), "r"(a3), "r"(b0), "r"(b1));
}

// ---------------- mask dtype detection ---------------------------------------
__global__ void detect_mask_k(const unsigned char* __restrict__ m){
    __shared__ int s_f1, s_f3, s_nzna, s_oddw;
    if(threadIdx.x==0){ s_f1=0; s_f3=0; s_nzna=0; s_oddw=0; }
    __syncthreads();
    for(int i=threadIdx.x; i<4096; i+=blockDim.x){
        unsigned char b = m[i];
        int off = i & 3;
        if(b){
            if(off==1 && b==0x3F) atomicOr(&s_f1, 1);
            if(off==3 && b==0x3F) atomicOr(&s_f3, 1);
            if(off!=0)            atomicOr(&s_nzna, 1);
        }
    }
    const unsigned int* w = (const unsigned int*)m;
    for(int i=threadIdx.x; i<1024; i+=blockDim.x){
        if((i & 1) && w[i]) atomicOr(&s_oddw, 1);
    }
    __syncthreads();
    if(threadIdx.x==0){
        int fmt;
        if(s_f1)        fmt = 3;
        else if(s_f3)   fmt = 2;
        else if(s_nzna) fmt = 0;
        else if(s_oddw) fmt = 1;
        else            fmt = 4;
        g_mask_fmt = fmt;
    }
}

__device__ __forceinline__ int mask_at(const void* p, long r, int fmt){
    switch(fmt){
        case 0: return ((const unsigned char*)p)[r] != 0;
        case 1: return ((const int*)p)[r] != 0;
        case 2: return ((const float*)p)[r] != 0.f;
        case 3: return ((const unsigned short*)p)[r] != 0;
        default:return ((const long long*)p)[r] != 0;
    }
}

// ---------------- prep -------------------------------------------------------
__global__ void basis_k(){
    int t = blockIdx.x*blockDim.x + threadIdx.x;
    if(t >= 648) return;
    int p = t/54, z = t%54;
    int ef = (p<6) ? p : (p+42);
    int m = (ef*z) % 54;
    double th = 6.283185307179586476925286766559 * (double)m / 54.0;
    d_c12[t] = (float)cos(th);
    d_s12[t] = (float)sin(th);
}

__global__ void zero_stats_k(){ g_stats[0]=0.0; g_stats[1]=0.0; }

__global__ void repack_k(const float* __restrict__ wr, const float* __restrict__ wi){
    long idx = (long)blockIdx.x*256 + threadIdx.x;
    if(idx >= 25560576L) return;
    long x = idx;
    int o = (int)(x%86); x/=86;
    int i = (int)(x%86); x/=86;
    int mloc = (int)(x%216); x/=216;
    long lb = x;
    long src = ((lb*86 + i)*86 + o)*216 + mloc;
    g_wp[idx] = make_float2(wr[src], wi[src]);
}

// ---------------- lift (zero-pad fused) ---------------------------------------
__global__ void lift_k(const float* __restrict__ df, const float* __restrict__ xout,
                       const float* __restrict__ w, const float* __restrict__ b){
    int n = blockIdx.x*256 + threadIdx.x;
    int c = blockIdx.y;
    if(n >= S3) return;
    int i = n/S2, j = (n/S)%S, k = n%S;
    float v = 0.f;
    if(i < 48 && j < 48 && k < 48){
        int n48 = (i*48 + j)*48 + k;
        float f0 = df[n48], f1 = df[NOUT + n48];
        float f2 = xout[n48*3+0], f3 = xout[n48*3+1], f4 = xout[n48*3+2];
        const float* wr = &w[c*5];
        v = b[c] + wr[0]*f0 + wr[1]*f1 + wr[2]*f2 + wr[3]*f3 + wr[4]*f4;
    }
    g_h[(size_t)c*S3 + n] = v;
}

// ---------------- tensor GEMM: C[M,N] = act(W[M,K](lda) @ X[K,N] + bias) -----
// 128x128 block, BK=16, 8 warps (4m x 2n), warp tile 32x64, 3xTF32.
template<int ACT>
__global__ __launch_bounds__(256) void tgemm_k(
    const float* __restrict__ W, int lda,
    const float* __restrict__ X,
    const float* __restrict__ Bv, float* __restrict__ C,
    int M, int K, int N)
{
    __shared__ float As[2][16][136];   // [k][m], stride 136 -> conflict-free frag reads
    __shared__ float Bs[2][16][136];   // [k][n]
    const int bm = blockIdx.y*128, bn = blockIdx.x*128;
    const int tid = threadIdx.x;
    const int wid = tid>>5, lane = tid&31;
    const int gid = lane>>2, tig = lane&3;
    const int wm = (wid>>1)*32;        // 4 warps along m
    const int wn = (wid&1)*64;        // 2 warps along n

    float acc[2][8][4];
    #pragma unroll
    for(int a=0;a<2;a++)
        #pragma unroll
        for(int b=0;b<8;b++)
            #pragma unroll
            for(int c=0;c<4;c++) acc[a][b][c]=0.f;

    float  a_st[8];
    float4 b_st[2];
    const int am = tid>>1;             // 0..127
    const int ak = (tid&1)*8;          // 0 or 8
    const int bk = tid>>5;             // 0..7
    const int bc = lane*4;             // 0..124

    auto loadT = [&](int kt){
        int k0 = kt*16;
        int gm = bm + am;
        #pragma unroll
        for(int u=0;u<8;u++){
            int gk = k0 + ak + u;
            a_st[u] = (gm < M && gk < K) ? W[(size_t)gm*lda + gk] : 0.f;
        }
        #pragma unroll
        for(int v=0;v<2;v++){
            int gk = k0 + bk + v*8;
            int gn = bn + bc;
            if(gk < K && gn + 3 < N){
                b_st[v] = *(const float4*)&X[(size_t)gk*N + gn];
            } else {
                b_st[v].x = (gk<K && gn+0<N) ? X[(size_t)gk*N + gn+0] : 0.f;
                b_st[v].y = (gk<K && gn+1<N) ? X[(size_t)gk*N + gn+1] : 0.f;
                b_st[v].z = (gk<K && gn+2<N) ? X[(size_t)gk*N + gn+2] : 0.f;
                b_st[v].w = (gk<K && gn+3<N) ? X[(size_t)gk*N + gn+3] : 0.f;
            }
        }
    };
    auto storeT = [&](int b){
        #pragma unroll
        for(int u=0;u<8;u++) As[b][ak+u][am] = a_st[u];
        #pragma unroll
        for(int v=0;v<2;v++) *(float4*)&Bs[b][bk+v*8][bc] = b_st[v];
    };
    auto comp = [&](int b){
        #pragma unroll
        for(int ko=0; ko<16; ko+=8){
            unsigned ah[2][4], al[2][4], bh[8][2], bl[8][2];
            #pragma unroll
            for(int mt=0; mt<2; mt++){
                int r0 = wm + mt*16 + gid;
                float f0 = As[b][ko+tig  ][r0];
                float f1 = As[b][ko+tig  ][r0+8];
                float f2 = As[b][ko+tig+4][r0];
                float f3 = As[b][ko+tig+4][r0+8];
                ah[mt][0]=cvt_tf32(f0); al[mt][0]=cvt_tf32(f0-__uint_as_float(ah[mt][0]));
                ah[mt][1]=cvt_tf32(f1); al[mt][1]=cvt_tf32(f1-__uint_as_float(ah[mt][1]));
                ah[mt][2]=cvt_tf32(f2); al[mt][2]=cvt_tf32(f2-__uint_as_float(ah[mt][2]));
                ah[mt][3]=cvt_tf32(f3); al[mt][3]=cvt_tf32(f3-__uint_as_float(ah[mt][3]));
            }
            #pragma unroll
            for(int nt=0; nt<8; nt++){
                int cn = wn + nt*8 + gid;
                float g0 = Bs[b][ko+tig  ][cn];
                float g1 = Bs[b][ko+tig+4][cn];
                bh[nt][0]=cvt_tf32(g0); bl[nt][0]=cvt_tf32(g0-__uint_as_float(bh[nt][0]));
                bh[nt][1]=cvt_tf32(g1); bl[nt][1]=cvt_tf32(g1-__uint_as_float(bh[nt][1]));
            }
            #pragma unroll
            for(int mt=0;mt<2;mt++)
                #pragma unroll
                for(int nt=0;nt<8;nt++){
                    mma8(acc[mt][nt], ah[mt][0],ah[mt][1],ah[mt][2],ah[mt][3], bh[nt][0],bh[nt][1]);
                    mma8(acc[mt][nt], ah[mt][0],ah[mt][1],ah[mt][2],ah[mt][3], bl[nt][0],bl[nt][1]);
                    mma8(acc[mt][nt], al[mt][0],al[mt][1],al[mt][2],al[mt][3], bh[nt][0],bh[nt][1]);
                }
        }
    };

    int ntiles = (K+15)>>4;
    loadT(0); storeT(0);
    __syncthreads();
    int buf = 0;
    for(int t=1; t<ntiles; t++){
        loadT(t);
        comp(buf);
        storeT(buf^1);
        __syncthreads();
        buf ^= 1;
    }
    comp(buf);

    // epilogue
    #pragma unroll
    for(int mt=0; mt<2; mt++){
        int r0 = bm + wm + mt*16 + gid;
        int r1 = r0 + 8;
        float bias0 = (r0 < M && Bv) ? Bv[r0] : 0.f;
        float bias1 = (r1 < M && Bv) ? Bv[r1] : 0.f;
        #pragma unroll
        for(int nt=0; nt<8; nt++){
            int gn = bn + wn + nt*8 + tig*2;
            float v0 = acc[mt][nt][0] + bias0;
            float v1 = acc[mt][nt][1] + bias0;
            float v2 = acc[mt][nt][2] + bias1;
            float v3 = acc[mt][nt][3] + bias1;
            if(ACT){ v0=gelu_f(v0); v1=gelu_f(v1); v2=gelu_f(v2); v3=gelu_f(v3); }
            if(r0 < M){
                if(gn   < N) C[(size_t)r0*N + gn]   = v0;
                if(gn+1 < N) C[(size_t)r0*N + gn+1] = v1;
            }
            if(r1 < M){
                if(gn   < N) C[(size_t)r1*N + gn]   = v2;
                if(gn+1 < N) C[(size_t)r1*N + gn+1] = v3;
            }
        }
    }
}

// ---------------- partial DFT chain -----------------------------------------
__global__ void dft_z_k(const float* __restrict__ h){
    __shared__ float sh[32*54];
    __shared__ float bc[324], bs[324];
    int t = threadIdx.x;                // 192
    long rowbase = (long)blockIdx.x*32;
    for(int i=t;i<324;i+=192){ bc[i]=d_c12[i]; bs[i]=d_s12[i]; }
    long gbase = rowbase*54;
    const long TOT = (long)CH*S2*54;
    for(int i=t;i<32*54;i+=192){
        long g = gbase + i;
        sh[i] = (g < TOT) ? h[g] : 0.f;
    }
    __syncthreads();
    int r = t/6, kz = t%6;
    long row = rowbase + r;
    if(row < (long)CH*S2){
        float re=0.f, im=0.f;
        const float* x = &sh[r*54];
        #pragma unroll
        for(int z=0;z<54;z++){
            float v = x[z];
            re = fmaf(v, bc[kz*54+z], re);
            im = fmaf(-v, bs[kz*54+z], im);
        }
        g_A1[row*6+kz] = make_float2(re, im);
    }
}

__global__ void dft_y_k(){
    __shared__ float2 sh[324];
    int t = threadIdx.x;                // 128
    int cx = blockIdx.x;
    const float2* src = g_A1 + (size_t)cx*324;
    for(int i=t;i<324;i+=128) sh[i] = src[i];
    __syncthreads();
    if(t < 72){
        int ky = t/6, kz = t%6;
        float re=0.f, im=0.f;
        for(int y=0;y<54;y++){
            float2 v = sh[y*6+kz];
            float c = d_c12[ky*54+y], s = d_s12[ky*54+y];
            re += v.x*c + v.y*s;
            im += v.y*c - v.x*s;
        }
        g_A2[(size_t)cx*72 + t] = make_float2(re, im);
    }
}

__global__ void dft_x_k(){
    __shared__ float2 sh[S*Q72];
    int t = threadIdx.x;                // 256
    int c = blockIdx.x;
    const float2* src = g_A2 + (size_t)c*(S*Q72);
    for(int i=t;i<S*Q72;i+=256) sh[i] = src[i];
    __syncthreads();
    for(int u=t; u<NMODE; u+=256){
        int kx = u/72, q = u%72;
        float re=0.f, im=0.f;
        for(int x=0;x<54;x++){
            float2 v = sh[x*72+q];
            float c = d_c12[kx*54+x], s = d_s12[kx*54+x];
            re += v.x*c + v.y*s;
            im += v.y*c - v.x*s;
        }
        g_A3[(size_t)c*NMODE + u] = make_float2(re, im);
    }
}

__global__ void mix_k(const float2* __restrict__ wp){
    __shared__ float2 a[86];
    int m = blockIdx.x;                 // 864
    int t = threadIdx.x;                // 96
    int kx = m/72, ky = (m%72)/6, kz = m%6;
    if(t < 86) a[t] = g_A3[(size_t)t*NMODE + m];
    __syncthreads();
    if(t < 86){
        int cblk = (kx>=6)*2 + (ky>=6);
        int mloc = (kx%6)*36 + (ky%6)*6 + kz;
        const float2* w = wp + ((size_t)cblk*216 + mloc)*7396 + t;
        float re=0.f, im=0.f;
        for(int i=0;i<86;i++){
            float2 av = a[i];
            float2 wv = w[(size_t)i*86];
            re += av.x*wv.x - av.y*wv.y;
            im += av.x*wv.y + av.y*wv.x;
        }
        g_M3[(size_t)t*NMODE + m] = make_float2(re, im);
    }
}

__global__ void inv_x_k(){
    __shared__ float2 sh[NMODE];
    int t = threadIdx.x;                // 256
    int c = blockIdx.x;
    for(int i=t;i<NMODE;i+=256) sh[i] = g_M3[(size_t)c*NMODE + i];
    __syncthreads();
    for(int u=t; u<S*Q72; u+=256){
        int x = u/72, q = u%72;
        float re=0.f, im=0.f;
        #pragma unroll
        for(int p=0;p<12;p++){
            float2 v = sh[p*72+q];
            float cc = d_c12[p*54+x], s = d_s12[p*54+x];
            re += v.x*cc - v.y*s;
            im += v.x*s  + v.y*cc;
        }
        g_B2[(size_t)c*(S*Q72) + u] = make_float2(re, im);
    }
}

__global__ void inv_y_k(){
    __shared__ float2 sh[72];
    int t = threadIdx.x;                // 128
    int cx = blockIdx.x;
    if(t < 72) sh[t] = g_B2[(size_t)cx*72 + t];
    __syncthreads();
    for(int u=t; u<324; u+=128){
        int y = u/6, kz = u%6;
        float re=0.f, im=0.f;
        #pragma unroll
        for(int ky=0;ky<12;ky++){
            float2 v = sh[ky*6+kz];
            float cc = d_c12[ky*54+y], s = d_s12[ky*54+y];
            re += v.x*cc - v.y*s;
            im += v.x*s  + v.y*cc;
        }
        g_B1[(size_t)cx*324 + u] = make_float2(re, im);
    }
}

__global__ void inv_z_k(){
    __shared__ float2 sh[324];
    int t = threadIdx.x;                // 256
    int cx = blockIdx.x;
    for(int i=t;i<324;i+=256) sh[i] = g_B1[(size_t)cx*324 + i];
    __syncthreads();
    const float inv = 1.0f/157464.0f;
    for(int u=t; u<S2; u+=256){
        int y = u/54, z = u%54;
        const float2* b = &sh[y*6];
        float v = b[0].x;
        #pragma unroll
        for(int kz=1;kz<6;kz++){
            float cc = d_c12[kz*54+z], s = d_s12[kz*54+z];
            v += 2.f*(b[kz].x*cc - b[kz].y*s);
        }
        g_hf[(size_t)cx*S2 + u] = v*inv;
    }
}

// ---------------- group-norm stats + combine ----------------------------------
__global__ void reduce_stats_k(const float* __restrict__ x, int n){
    const float4* x4 = (const float4*)x;
    int n4 = n >> 2;
    float s=0.f, s2=0.f;
    for(long i=(long)blockIdx.x*blockDim.x+threadIdx.x; i<n4; i+=(long)gridDim.x*blockDim.x){
        float4 v = x4[i];
        s += v.x+v.y+v.z+v.w;
        s2 = fmaf(v.x,v.x, fmaf(v.y,v.y, fmaf(v.z,v.z, fmaf(v.w,v.w, s2))));
    }
    #pragma unroll
    for(int o=16;o>0;o>>=1){
        s  += __shfl_down_sync(0xffffffffu, s, o);
        s2 += __shfl_down_sync(0xffffffffu, s2, o);
    }
    __shared__ double ds[8], ds2[8];
    int w = threadIdx.x>>5;
    if((threadIdx.x&31)==0){ ds[w]=(double)s; ds2[w]=(double)s2; }
    __syncthreads();
    if(threadIdx.x==0){
        double a=0,b=0;
        #pragma unroll
        for(int k=0;k<8;k++){ a+=ds[k]; b+=ds2[k]; }
        atomicAdd(&g_stats[0], a);
        atomicAdd(&g_stats[1], b);
    }
}

__global__ void combine_k(const float4* __restrict__ buf, const float4* __restrict__ add,
                          const float* __restrict__ gw, const float* __restrict__ gb,
                          float4* __restrict__ h, int actflag){
    long i = (long)blockIdx.x*blockDim.x + threadIdx.x;
    if(i >= (CS>>2)) return;
    double mu  = g_stats[0]/(double)CS;
    double var = g_stats[1]/(double)CS - mu*mu;
    float rs = (float)rsqrt(var + EPSGN);
    float fmu = (float)mu;
    int c = (int)((i<<2) / S3);
    float sw = rs*gw[c], sb = gb[c];
    float4 u = buf[i], a = add[i];
    float4 o;
    o.x = (u.x-fmu)*sw + sb + a.x;
    o.y = (u.y-fmu)*sw + sb + a.y;
    o.z = (u.z-fmu)*sw + sb + a.z;
    o.w = (u.w-fmu)*sw + sb + a.w;
    if(actflag){ o.x=gelu_f(o.x); o.y=gelu_f(o.y); o.z=gelu_f(o.z); o.w=gelu_f(o.w); }
    h[i] = o;
}

// ---------------- GNO head ----------------------------------------------------
__global__ void embed_t_k(const float* __restrict__ pts, float* __restrict__ out, int n){
    int i = blockIdx.x*blockDim.x + threadIdx.x;
    if(i >= n) return;
    #pragma unroll
    for(int d=0; d<3; d++){
        float x = pts[i*3+d];
        #pragma unroll
        for(int f=0; f<8; f++){
            float fr = powf(1e-4f, (float)f/8.0f);
            float a = x*fr;
            out[(size_t)(d*16+f)*n + i]     = cosf(a);
            out[(size_t)(d*16+8+f)*n + i]   = sinf(a);
        }
    }
}

__global__ void crop_k(){
    int n = blockIdx.x*256 + threadIdx.x;
    int c = blockIdx.y;
    if(n >= NOUT) return;
    int i = n/2304, j = (n/48)%48, k = n%48;
    g_fy[(size_t)n*CH + c] = g_h[((size_t)(c*S + i)*S + j)*S + k];
}

// k1[o][r] = gelu( Y1[o][nb_idx[r]] + Q1[o][r/24] )
__global__ void k1_fuse_k(const int* __restrict__ nb_idx){
    int r = blockIdx.x*256 + threadIdx.x;
    int idx = nb_idx[r];
    int i = r / KNB;
    const float* y = g_y1 + idx;
    const float* q = g_q1 + i;
    float* o = g_k1 + r;
    #pragma unroll 4
    for(int c=0; c<512; c++){
        float v = y[(size_t)c*NOUT] + q[(size_t)c*NIN];
        o[(size_t)c*RTOT] = gelu_f(v);
    }
}

__global__ void gno_reduce_k(const int* __restrict__ nb_idx, const void* __restrict__ nb_mask){
    int i = blockIdx.x;                 // NIN
    int c = threadIdx.x;                // 96 (86 active)
    __shared__ int sidx[KNB]; __shared__ int smask[KNB];
    if(c < KNB){
        int fmt = g_mask_fmt;
        sidx[c]  = nb_idx[i*KNB + c];
        smask[c] = mask_at(nb_mask, (long)i*KNB + c, fmt);
    }
    __syncthreads();
    if(c >= CH) return;
    float acc = 0.f; int cnt = 0;
    #pragma unroll
    for(int j=0; j<KNB; j++){
        if(smask[j]){
            cnt++;
            acc += g_k3[(size_t)c*RTOT + i*KNB + j] * g_fy[(size_t)sidx[j]*CH + c];
        }
    }
    float den = (float)(cnt > 1 ? cnt : 1);
    g_gv[(size_t)c*NIN + i] = acc/den;
}

__global__ void p2_k(const float* __restrict__ w, const float* __restrict__ b,
                     float* __restrict__ out){
    int i = blockIdx.x*256 + threadIdx.x;
    if(i >= NIN) return;
    float acc = b[0];
    #pragma unroll 8
    for(int f=0; f<256; f++) acc = fmaf(w[f], g_p1[(size_t)f*NIN + i], acc);
    out[i] = acc;
}

// ---------------- host orchestration -----------------------------------------
static void tgemm(const float* W, int lda, const float* X, const float* B, float* C,
                  int M, int K, int N, int act){
    dim3 grid((N+127)/128, (M+127)/128);
    if(act) tgemm_k<1><<<grid,256>>>(W,lda,X,B,C,M,K,N);
    else    tgemm_k<0><<<grid,256>>>(W,lda,X,B,C,M,K,N);
}

extern "C" void kernel_launch(void* const* d_in, const int* in_sizes, int n_in,
                              void* d_out, int out_size){
    const float* x_in   = (const float*)d_in[0];
    const float* x_out  = (const float*)d_in[1];
    const float* df     = (const float*)d_in[2];
    const int*   nb_idx = (const int*)  d_in[3];
    const void*  nb_mask= (const void*) d_in[4];
    const float* w_lift = (const float*)d_in[5];
    const float* b_lift = (const float*)d_in[6];
    const float* spec_wr= (const float*)d_in[7];
    const float* spec_wi= (const float*)d_in[8];
    const float* w_skip = (const float*)d_in[9];
    const float* b_skip = (const float*)d_in[10];
    const float* mlp1_w = (const float*)d_in[11];
    const float* mlp1_b = (const float*)d_in[12];
    const float* mlp2_w = (const float*)d_in[13];
    const float* mlp2_b = (const float*)d_in[14];
    const float* wms    = (const float*)d_in[15];
    const float* bms    = (const float*)d_in[16];
    const float* g1w    = (const float*)d_in[17];
    const float* g1b    = (const float*)d_in[18];
    const float* g2w    = (const float*)d_in[19];
    const float* g2b    = (const float*)d_in[20];
    const float* k1w    = (const float*)d_in[21];
    const float* k1b    = (const float*)d_in[22];
    const float* k2w    = (const float*)d_in[23];
    const float* k2b    = (const float*)d_in[24];
    const float* k3w    = (const float*)d_in[25];
    const float* k3b    = (const float*)d_in[26];
    const float* p1w    = (const float*)d_in[27];
    const float* p1b    = (const float*)d_in[28];
    const float* p2w    = (const float*)d_in[29];
    const float* p2b    = (const float*)d_in[30];
    float* out = (float*)d_out;

    float *ph, *pskip, *phf, *pt1, *pxoe, *pxie, *py1, *pq1, *pk1, *pk2, *pk3, *pgv, *pp1;
    float2 *pwp;
    cudaGetSymbolAddress((void**)&ph,    g_h);
    cudaGetSymbolAddress((void**)&pskip, g_skip);
    cudaGetSymbolAddress((void**)&phf,   g_hf);
    cudaGetSymbolAddress((void**)&pt1,   g_t1);
    cudaGetSymbolAddress((void**)&pxoe,  g_xoe);
    cudaGetSymbolAddress((void**)&pxie,  g_xie);
    cudaGetSymbolAddress((void**)&py1,   g_y1);
    cudaGetSymbolAddress((void**)&pq1,   g_q1);
    cudaGetSymbolAddress((void**)&pk1,   g_k1);
    cudaGetSymbolAddress((void**)&pk2,   g_k2);
    cudaGetSymbolAddress((void**)&pk3,   g_k3);
    cudaGetSymbolAddress((void**)&pgv,   g_gv);
    cudaGetSymbolAddress((void**)&pp1,   g_p1);
    cudaGetSymbolAddress((void**)&pwp,   g_wp);

    // prep
    basis_k<<<2,384>>>();
    detect_mask_k<<<1,256>>>((const unsigned char*)nb_mask);
    repack_k<<<(int)((25560576L+255)/256),256>>>(spec_wr, spec_wi);
    {
        dim3 g((S3+255)/256, CH);
        lift_k<<<g,256>>>(df, x_out, w_lift, b_lift);
    }

    // FNO layers
    for(int l=0;l<4;l++){
        int act = (l<3) ? 1 : 0;
        tgemm(w_skip + (size_t)l*CH*CH, CH, ph, b_skip + l*CH, pskip, CH, CH, S3, 0);
        dft_z_k<<<(CH*S2+31)/32, 192>>>(ph);
        dft_y_k<<<CH*S, 128>>>();
        dft_x_k<<<CH, 256>>>();
        mix_k<<<NMODE, 96>>>(pwp + (size_t)l*WLAYER);
        inv_x_k<<<CH, 256>>>();
        inv_y_k<<<CH*S, 128>>>();
        inv_z_k<<<CH*S, 256>>>();
        zero_stats_k<<<1,1>>>();
        reduce_stats_k<<<2048,256>>>(phf, CS);
        combine_k<<<((CS>>2)+255)/256,256>>>((const float4*)phf,(const float4*)pskip,
                                             g1w + l*CH, g1b + l*CH, (float4*)ph, act);
        tgemm(wms    + (size_t)l*CH*CH, CH, ph,  bms    + l*CH, pskip, CH, CH, S3, 0);
        tgemm(mlp1_w + (size_t)l*CH*CH, CH, ph,  mlp1_b + l*CH, pt1,   CH, CH, S3, 1);
        tgemm(mlp2_w + (size_t)l*CH*CH, CH, pt1, mlp2_b + l*CH, phf,   CH, CH, S3, 0);
        zero_stats_k<<<1,1>>>();
        reduce_stats_k<<<2048,256>>>(phf, CS);
        combine_k<<<((CS>>2)+255)/256,256>>>((const float4*)phf,(const float4*)pskip,
                                             g2w + l*CH, g2b + l*CH, (float4*)ph, act);
    }

    // crop f_y
    {
        dim3 g((NOUT+255)/256, CH);
        crop_k<<<g,256>>>();
    }

    // transposed embeddings
    embed_t_k<<<(NOUT+127)/128,128>>>(x_out, pxoe, NOUT);
    embed_t_k<<<(NIN +127)/128,128>>>(x_in,  pxie, NIN);

    // GNO kernel MLP: k1 split into Y1 (grid part) + Q1 (query part, bias folded)
    tgemm(k1w,      96, pxoe, 0,   py1, 512, 48, NOUT, 0);
    tgemm(k1w + 48, 96, pxie, k1b, pq1, 512, 48, NIN,  0);
    k1_fuse_k<<<RTOT/256,256>>>(nb_idx);
    tgemm(k2w, 512, pk1, k2b, pk2, 256, 512, RTOT, 1);
    tgemm(k3w, 256, pk2, k3b, pk3,  CH, 256, RTOT, 0);

    // masked neighbor reduce
    gno_reduce_k<<<NIN, 96>>>(nb_idx, nb_mask);

    // projection MLP
    tgemm(p1w, CH, pgv, p1b, pp1, 256, CH, NIN, 1);
    p2_k<<<(NIN+255)/256,256>>>(p2w, p2b, out);
}